// round 2
// baseline (speedup 1.0000x reference)
#include <cuda_runtime.h>
#include <cuda_bf16.h>

typedef unsigned long long ull;

// ---------------------------------------------------------------------------
// Problem constants
// ---------------------------------------------------------------------------
#define BB    64
#define TT    512
#define HHH   128
#define MMM   (BB * TT)        /* 32768 rows (b,t) */

// ---------------------------------------------------------------------------
// Scratch: static __device__ arrays (allocation-free per harness rules)
// ---------------------------------------------------------------------------
__device__ float g_x0[MMM * 128];          // embedded input      [32768][128]
__device__ float g_xg[2u * MMM * 512];     // gate preactivations [2][32768][512]
__device__ float g_ya[MMM * 256];          // layer output ping   [32768][256]
__device__ float g_yb[MMM * 256];          // layer output pong   [32768][256]
__device__ float g_ylast[BB * 256];        // final-layer last-t  [64][256]

// ---------------------------------------------------------------------------
// f32x2 packed-math helpers (FFMA2 — only reachable via PTX)
// ---------------------------------------------------------------------------
__device__ __forceinline__ ull pk2(float lo, float hi) {
    ull r;
    asm("mov.b64 %0, {%1, %2};" : "=l"(r) : "f"(lo), "f"(hi));
    return r;
}
__device__ __forceinline__ ull fma2(ull a, ull b, ull c) {
    ull d;
    asm("fma.rn.f32x2 %0, %1, %2, %3;" : "=l"(d) : "l"(a), "l"(b), "l"(c));
    return d;
}
__device__ __forceinline__ float2 upk2(ull v) {
    float2 f;
    asm("mov.b64 {%0, %1}, %2;" : "=f"(f.x), "=f"(f.y) : "l"(v));
    return f;
}

// ---------------------------------------------------------------------------
// Kernel 1: embedding gather  x0[m][e] = emb[X[m]][e]
// ---------------------------------------------------------------------------
__global__ void embed_k(const int* __restrict__ X,
                        const float* __restrict__ emb,
                        float* __restrict__ out) {
    int i = blockIdx.x * blockDim.x + threadIdx.x;   // 0 .. 32768*32-1
    int m  = i >> 5;
    int e4 = (i & 31) << 2;
    int v  = X[m];
    *reinterpret_cast<float4*>(&out[(size_t)m * 128 + e4]) =
        *reinterpret_cast<const float4*>(&emb[(size_t)v * 128 + e4]);
}

// ---------------------------------------------------------------------------
// Kernel 2: input GEMM   C[d][m][n] = sum_k X[m][k]*W[d][n][k] + bi[d][n]+bh[d][n]
//   X: [M][K]  W: [2][512][K]  C: [2][M][512]
//   Tiles: 128x128x16, 256 threads, 8x8 microtile, f32x2 accumulation.
// ---------------------------------------------------------------------------
#define GBM 128
#define GBN 128
#define GBK 16

__global__ __launch_bounds__(256)
void gemm_xw(const float* __restrict__ X,
             const float* __restrict__ Wfull,
             const float* __restrict__ bi,
             const float* __restrict__ bh,
             float* __restrict__ C,
             int K) {
    const int d  = blockIdx.z;
    const float* Wd = Wfull + (size_t)d * 512 * K;
    float* Cd       = C     + (size_t)d * MMM * 512;

    __shared__ float As[GBK][GBM];
    __shared__ float Bs[GBK][GBN];

    const int m0 = blockIdx.y * GBM;
    const int n0 = blockIdx.x * GBN;
    const int tid = threadIdx.x;
    const int tx = tid & 15;        // n direction
    const int ty = tid >> 4;        // m direction

    ull acc[8][4];
#pragma unroll
    for (int i = 0; i < 8; i++)
#pragma unroll
        for (int jp = 0; jp < 4; jp++) acc[i][jp] = 0ull;

    for (int k0 = 0; k0 < K; k0 += GBK) {
        // --- load A tile (128 rows x 16 cols) -------------------------------
#pragma unroll
        for (int i = 0; i < 2; i++) {
            int f   = tid + i * 256;          // 0..511 float4 slots
            int row = f >> 2;
            int kq  = (f & 3) << 2;
            float4 v = *reinterpret_cast<const float4*>(
                &X[(size_t)(m0 + row) * K + k0 + kq]);
            As[kq + 0][row] = v.x;
            As[kq + 1][row] = v.y;
            As[kq + 2][row] = v.z;
            As[kq + 3][row] = v.w;
        }
        // --- load B tile (W rows n0..n0+127 x 16 cols) ----------------------
#pragma unroll
        for (int i = 0; i < 2; i++) {
            int f   = tid + i * 256;
            int row = f >> 2;
            int kq  = (f & 3) << 2;
            float4 v = *reinterpret_cast<const float4*>(
                &Wd[(size_t)(n0 + row) * K + k0 + kq]);
            Bs[kq + 0][row] = v.x;
            Bs[kq + 1][row] = v.y;
            Bs[kq + 2][row] = v.z;
            Bs[kq + 3][row] = v.w;
        }
        __syncthreads();

#pragma unroll
        for (int k = 0; k < GBK; k++) {
            float4 a0 = *reinterpret_cast<const float4*>(&As[k][ty * 8]);
            float4 a1 = *reinterpret_cast<const float4*>(&As[k][ty * 8 + 4]);
            const ull* bp = reinterpret_cast<const ull*>(&Bs[k][tx * 8]);
            ull b0 = bp[0], b1 = bp[1], b2 = bp[2], b3 = bp[3];
            float aa[8] = {a0.x, a0.y, a0.z, a0.w, a1.x, a1.y, a1.z, a1.w};
#pragma unroll
            for (int i = 0; i < 8; i++) {
                ull ap = pk2(aa[i], aa[i]);
                acc[i][0] = fma2(ap, b0, acc[i][0]);
                acc[i][1] = fma2(ap, b1, acc[i][1]);
                acc[i][2] = fma2(ap, b2, acc[i][2]);
                acc[i][3] = fma2(ap, b3, acc[i][3]);
            }
        }
        __syncthreads();
    }

    // --- epilogue: add biases, store ---------------------------------------
    float biasn[8];
#pragma unroll
    for (int q = 0; q < 8; q++) {
        int n = n0 + tx * 8 + q;
        biasn[q] = bi[d * 512 + n] + bh[d * 512 + n];
    }
#pragma unroll
    for (int i = 0; i < 8; i++) {
        int m = m0 + ty * 8 + i;
#pragma unroll
        for (int jp = 0; jp < 4; jp++) {
            int n = n0 + tx * 8 + jp * 2;
            float2 v = upk2(acc[i][jp]);
            float2 outv = make_float2(v.x + biasn[jp * 2], v.y + biasn[jp * 2 + 1]);
            *reinterpret_cast<float2*>(&Cd[(size_t)m * 512 + n]) = outv;
        }
    }
}

// ---------------------------------------------------------------------------
// Kernel 3: LSTM recurrence, one CTA per (dir, batch).
//   xg:  [2][32768][512] preactivations (biases already included)
//   whh: [2][512][128]
//   hx0/cx0: pointers at this layer's base: [(d*64+b)*128 + j]
//   y: if !final: [32768][256]   (y[(b*512+t)*256 + d*128 + j])
//      if final:  [64][256]      (only last-timestep h stored)
// Gate rows (torch order): i=0..127, f=128..255, g=256..383, o=384..511.
// Smem holds i,f,g transposed (pad 129); o-gate weights live in registers.
// ---------------------------------------------------------------------------
#define WS_STRIDE 129
#define WS_GATE   (128 * WS_STRIDE)
#define LSTM_SMEM ((3 * WS_GATE + 2 * 128) * 4)

__global__ __launch_bounds__(128, 1)
void lstm_layer(const float* __restrict__ xg,
                const float* __restrict__ whh,
                const float* __restrict__ hx0,
                const float* __restrict__ cx0,
                float* __restrict__ y,
                int final_layer) {
    extern __shared__ float sm[];
    float* Ws = sm;                       // [3][128(k)][129] : Ws[g][k][j] = whh[d][g*128+j][k]
    float* hb = sm + 3 * WS_GATE;         // two 128-float h buffers

    const int d = blockIdx.x >> 6;
    const int b = blockIdx.x & 63;
    const int j = threadIdx.x;            // 0..127

    const float* W = whh + (size_t)d * 512 * 128;

    // ---- one-time: load i,f,g gates into smem, transposed -----------------
    for (int r = 0; r < 384; r++) {
        float v = W[(size_t)r * 128 + j];       // coalesced
        int gate = r >> 7;
        int rr   = r & 127;
        Ws[gate * WS_GATE + j * WS_STRIDE + rr] = v;   // stride 129 -> conflict-free
    }
    // ---- one-time: o-gate row j into registers ----------------------------
    float wo[128];
#pragma unroll
    for (int k = 0; k < 128; k++) wo[k] = W[(size_t)(384 + j) * 128 + k];

    // ---- init h, c --------------------------------------------------------
    float c = cx0[(size_t)(d * 64 + b) * 128 + j];
    hb[j] = hx0[(size_t)(d * 64 + b) * 128 + j];
    __syncthreads();

    const int t0 = d ? (TT - 1) : 0;
    const int dt = d ? -1 : 1;
    const int nsteps = (final_layer && d) ? 1 : TT;

    const float* xgb = xg + ((size_t)d * MMM + (size_t)b * TT) * 512;

    float xi = xgb[(size_t)t0 * 512 + j];
    float xf = xgb[(size_t)t0 * 512 + 128 + j];
    float xgv = xgb[(size_t)t0 * 512 + 256 + j];
    float xo = xgb[(size_t)t0 * 512 + 384 + j];

    int pb = 0;
    for (int s = 0; s < nsteps; s++) {
        const int t = t0 + s * dt;
        float nxi = 0.f, nxf = 0.f, nxg = 0.f, nxo = 0.f;
        if (s + 1 < nsteps) {
            const size_t base = (size_t)(t + dt) * 512;
            nxi = xgb[base + j];
            nxf = xgb[base + 128 + j];
            nxg = xgb[base + 256 + j];
            nxo = xgb[base + 384 + j];
        }

        const float* h = hb + pb * 128;
        float ai = xi, af = xf, ag = xgv, ao = xo;
#pragma unroll
        for (int k = 0; k < 128; k++) {
            float hk = h[k];
            ai = fmaf(Ws[0 * WS_GATE + k * WS_STRIDE + j], hk, ai);
            af = fmaf(Ws[1 * WS_GATE + k * WS_STRIDE + j], hk, af);
            ag = fmaf(Ws[2 * WS_GATE + k * WS_STRIDE + j], hk, ag);
            ao = fmaf(wo[k], hk, ao);
        }

        float ig = 1.f / (1.f + expf(-ai));
        float fg = 1.f / (1.f + expf(-af));
        float og = 1.f / (1.f + expf(-ao));
        c = fg * c + ig * tanhf(ag);
        float hn = og * tanhf(c);

        pb ^= 1;
        hb[pb * 128 + j] = hn;
        __syncthreads();

        if (!final_layer) {
            y[((size_t)b * TT + t) * 256 + d * 128 + j] = hn;
        } else if (s == nsteps - 1) {
            y[(size_t)b * 256 + d * 128 + j] = hn;
        }

        xi = nxi; xf = nxf; xgv = nxg; xo = nxo;
    }
}

// ---------------------------------------------------------------------------
// Kernel 4: linear head   out[b] = dot(ylast[b], lin_w) + lin_b
// ---------------------------------------------------------------------------
__global__ void head_k(const float* __restrict__ ylast,
                       const float* __restrict__ w,
                       const float* __restrict__ bsc,
                       float* __restrict__ out) {
    int b = blockIdx.x;
    int l = threadIdx.x;          // 0..31
    float s = 0.f;
#pragma unroll
    for (int k = l; k < 256; k += 32) s += ylast[(size_t)b * 256 + k] * w[k];
#pragma unroll
    for (int o = 16; o; o >>= 1) s += __shfl_xor_sync(0xffffffffu, s, o);
    if (l == 0) out[b] = s + bsc[0];
}

// ---------------------------------------------------------------------------
// Host launcher
// ---------------------------------------------------------------------------
extern "C" void kernel_launch(void* const* d_in, const int* in_sizes, int n_in,
                              void* d_out, int out_size) {
    const int*   X     = (const int*)d_in[0];
    const float* emb   = (const float*)d_in[1];
    const float* hx    = (const float*)d_in[2];
    const float* cx    = (const float*)d_in[3];
    const float* lin_w = (const float*)d_in[4];
    const float* lin_b = (const float*)d_in[5];
    const float* w_ih[3] = {(const float*)d_in[6],  (const float*)d_in[10], (const float*)d_in[14]};
    const float* w_hh[3] = {(const float*)d_in[7],  (const float*)d_in[11], (const float*)d_in[15]};
    const float* b_ih[3] = {(const float*)d_in[8],  (const float*)d_in[12], (const float*)d_in[16]};
    const float* b_hh[3] = {(const float*)d_in[9],  (const float*)d_in[13], (const float*)d_in[17]};
    float* out = (float*)d_out;

    float *x0, *xgp, *ya, *yb, *ylast;
    cudaGetSymbolAddress((void**)&x0,    g_x0);
    cudaGetSymbolAddress((void**)&xgp,   g_xg);
    cudaGetSymbolAddress((void**)&ya,    g_ya);
    cudaGetSymbolAddress((void**)&yb,    g_yb);
    cudaGetSymbolAddress((void**)&ylast, g_ylast);

    cudaFuncSetAttribute(lstm_layer,
                         cudaFuncAttributeMaxDynamicSharedMemorySize, LSTM_SMEM);

    // 1) embed
    embed_k<<<(MMM * 32) / 256, 256>>>(X, emb, x0);

    // 2) layer 0
    gemm_xw<<<dim3(512 / GBN, MMM / GBM, 2), 256>>>(x0, w_ih[0], b_ih[0], b_hh[0], xgp, 128);
    lstm_layer<<<128, 128, LSTM_SMEM>>>(xgp, w_hh[0], hx + 0 * BB * 128, cx + 0 * BB * 128, ya, 0);

    // 3) layer 1
    gemm_xw<<<dim3(512 / GBN, MMM / GBM, 2), 256>>>(ya, w_ih[1], b_ih[1], b_hh[1], xgp, 256);
    lstm_layer<<<128, 128, LSTM_SMEM>>>(xgp, w_hh[1], hx + 2 * BB * 128, cx + 2 * BB * 128, yb, 0);

    // 4) layer 2 (final: fwd full scan stores only t=T-1; bwd is a single step)
    gemm_xw<<<dim3(512 / GBN, MMM / GBM, 2), 256>>>(yb, w_ih[2], b_ih[2], b_hh[2], xgp, 256);
    lstm_layer<<<128, 128, LSTM_SMEM>>>(xgp, w_hh[2], hx + 4 * BB * 128, cx + 4 * BB * 128, ylast, 1);

    // 5) head
    head_k<<<BB, 32>>>(ylast, lin_w, lin_b, out);
}

// round 3
// speedup vs baseline: 1.3573x; 1.3573x over previous
#include <cuda_runtime.h>
#include <cuda_bf16.h>

typedef unsigned long long ull;

// ---------------------------------------------------------------------------
// Problem constants
// ---------------------------------------------------------------------------
#define BB    64
#define TT    512
#define MMM   (BB * TT)        /* 32768 rows (b,t) */

// ---------------------------------------------------------------------------
// Scratch (static __device__ arrays -- allocation-free)
// ---------------------------------------------------------------------------
__device__ float g_x0[MMM * 128];
__device__ float g_xg[2u * MMM * 512];
__device__ float g_ya[MMM * 256];
__device__ float g_yb[MMM * 256];
__device__ float g_ylast[BB * 256];

// ---------------------------------------------------------------------------
// f32x2 packed helpers
// ---------------------------------------------------------------------------
__device__ __forceinline__ ull pk2(float lo, float hi) {
    ull r; asm("mov.b64 %0, {%1, %2};" : "=l"(r) : "f"(lo), "f"(hi)); return r;
}
__device__ __forceinline__ ull fma2(ull a, ull b, ull c) {
    ull d; asm("fma.rn.f32x2 %0, %1, %2, %3;" : "=l"(d) : "l"(a), "l"(b), "l"(c)); return d;
}
__device__ __forceinline__ ull add2(ull a, ull b) {
    ull d; asm("add.rn.f32x2 %0, %1, %2;" : "=l"(d) : "l"(a), "l"(b)); return d;
}
__device__ __forceinline__ float2 upk2(ull v) {
    float2 f; asm("mov.b64 {%0, %1}, %2;" : "=f"(f.x), "=f"(f.y) : "l"(v)); return f;
}
__device__ __forceinline__ float hsum2(ull v) { float2 f = upk2(v); return f.x + f.y; }

__device__ __forceinline__ float sig_f(float x) {
    return __fdividef(1.f, 1.f + __expf(-x));
}
__device__ __forceinline__ float tanh_f(float x) {
    // 1 - 2/(1+exp(2x)) : stable at both extremes (inf arithmetic safe)
    return 1.f - __fdividef(2.f, 1.f + __expf(2.f * x));
}

// ---------------------------------------------------------------------------
// Kernel 1: embedding gather
// ---------------------------------------------------------------------------
__global__ void embed_k(const int* __restrict__ X,
                        const float* __restrict__ emb,
                        float* __restrict__ out) {
    int i = blockIdx.x * blockDim.x + threadIdx.x;
    int m  = i >> 5;
    int e4 = (i & 31) << 2;
    int v  = X[m];
    *reinterpret_cast<float4*>(&out[(size_t)m * 128 + e4]) =
        *reinterpret_cast<const float4*>(&emb[(size_t)v * 128 + e4]);
}

// ---------------------------------------------------------------------------
// Kernel 2: input GEMM, double-buffered smem + register prefetch.
//   C[d][m][n] = sum_k X[m][k]*W[d][n][k] + bi[d][n] + bh[d][n]
// ---------------------------------------------------------------------------
#define GBM 128
#define GBN 128
#define GBK 16

__global__ __launch_bounds__(256)
void gemm_xw(const float* __restrict__ X,
             const float* __restrict__ Wfull,
             const float* __restrict__ bi,
             const float* __restrict__ bh,
             float* __restrict__ C,
             int K) {
    const int d  = blockIdx.z;
    const float* Wd = Wfull + (size_t)d * 512 * K;
    float* Cd       = C     + (size_t)d * MMM * 512;

    __shared__ float As[2][GBK][GBM];
    __shared__ float Bs[2][GBK][GBN];

    const int m0 = blockIdx.y * GBM;
    const int n0 = blockIdx.x * GBN;
    const int tid = threadIdx.x;
    const int tx = tid & 15;
    const int ty = tid >> 4;

    // loader indices: 512 float4 slots per tile, 2 per thread
    const int r0l = tid >> 2,          kq0 = (tid & 3) << 2;
    const int r1l = (tid + 256) >> 2,  kq1 = ((tid + 256) & 3) << 2;

    ull acc[8][4];
#pragma unroll
    for (int i = 0; i < 8; i++)
#pragma unroll
        for (int jp = 0; jp < 4; jp++) acc[i][jp] = 0ull;

    // preload tile 0 into regs
    float4 av0 = *reinterpret_cast<const float4*>(&X [(size_t)(m0 + r0l) * K + kq0]);
    float4 av1 = *reinterpret_cast<const float4*>(&X [(size_t)(m0 + r1l) * K + kq1]);
    float4 bv0 = *reinterpret_cast<const float4*>(&Wd[(size_t)(n0 + r0l) * K + kq0]);
    float4 bv1 = *reinterpret_cast<const float4*>(&Wd[(size_t)(n0 + r1l) * K + kq1]);
    {
        As[0][kq0 + 0][r0l] = av0.x; As[0][kq0 + 1][r0l] = av0.y;
        As[0][kq0 + 2][r0l] = av0.z; As[0][kq0 + 3][r0l] = av0.w;
        As[0][kq1 + 0][r1l] = av1.x; As[0][kq1 + 1][r1l] = av1.y;
        As[0][kq1 + 2][r1l] = av1.z; As[0][kq1 + 3][r1l] = av1.w;
        Bs[0][kq0 + 0][r0l] = bv0.x; Bs[0][kq0 + 1][r0l] = bv0.y;
        Bs[0][kq0 + 2][r0l] = bv0.z; Bs[0][kq0 + 3][r0l] = bv0.w;
        Bs[0][kq1 + 0][r1l] = bv1.x; Bs[0][kq1 + 1][r1l] = bv1.y;
        Bs[0][kq1 + 2][r1l] = bv1.z; Bs[0][kq1 + 3][r1l] = bv1.w;
    }
    __syncthreads();

    int buf = 0;
    for (int k0 = 0; k0 < K; k0 += GBK) {
        const bool more = (k0 + GBK) < K;
        if (more) {
            const int kn = k0 + GBK;
            av0 = *reinterpret_cast<const float4*>(&X [(size_t)(m0 + r0l) * K + kn + kq0]);
            av1 = *reinterpret_cast<const float4*>(&X [(size_t)(m0 + r1l) * K + kn + kq1]);
            bv0 = *reinterpret_cast<const float4*>(&Wd[(size_t)(n0 + r0l) * K + kn + kq0]);
            bv1 = *reinterpret_cast<const float4*>(&Wd[(size_t)(n0 + r1l) * K + kn + kq1]);
        }

#pragma unroll
        for (int k = 0; k < GBK; k++) {
            float4 a0 = *reinterpret_cast<const float4*>(&As[buf][k][ty * 8]);
            float4 a1 = *reinterpret_cast<const float4*>(&As[buf][k][ty * 8 + 4]);
            const ull* bp = reinterpret_cast<const ull*>(&Bs[buf][k][tx * 8]);
            ull b0 = bp[0], b1 = bp[1], b2 = bp[2], b3 = bp[3];
            float aa[8] = {a0.x, a0.y, a0.z, a0.w, a1.x, a1.y, a1.z, a1.w};
#pragma unroll
            for (int i = 0; i < 8; i++) {
                ull ap = pk2(aa[i], aa[i]);
                acc[i][0] = fma2(ap, b0, acc[i][0]);
                acc[i][1] = fma2(ap, b1, acc[i][1]);
                acc[i][2] = fma2(ap, b2, acc[i][2]);
                acc[i][3] = fma2(ap, b3, acc[i][3]);
            }
        }

        if (more) {
            const int nb = buf ^ 1;
            As[nb][kq0 + 0][r0l] = av0.x; As[nb][kq0 + 1][r0l] = av0.y;
            As[nb][kq0 + 2][r0l] = av0.z; As[nb][kq0 + 3][r0l] = av0.w;
            As[nb][kq1 + 0][r1l] = av1.x; As[nb][kq1 + 1][r1l] = av1.y;
            As[nb][kq1 + 2][r1l] = av1.z; As[nb][kq1 + 3][r1l] = av1.w;
            Bs[nb][kq0 + 0][r0l] = bv0.x; Bs[nb][kq0 + 1][r0l] = bv0.y;
            Bs[nb][kq0 + 2][r0l] = bv0.z; Bs[nb][kq0 + 3][r0l] = bv0.w;
            Bs[nb][kq1 + 0][r1l] = bv1.x; Bs[nb][kq1 + 1][r1l] = bv1.y;
            Bs[nb][kq1 + 2][r1l] = bv1.z; Bs[nb][kq1 + 3][r1l] = bv1.w;
            __syncthreads();
            buf = nb;
        }
    }

    float biasn[8];
#pragma unroll
    for (int q = 0; q < 8; q++) {
        int n = n0 + tx * 8 + q;
        biasn[q] = bi[d * 512 + n] + bh[d * 512 + n];
    }
#pragma unroll
    for (int i = 0; i < 8; i++) {
        int m = m0 + ty * 8 + i;
#pragma unroll
        for (int jp = 0; jp < 4; jp++) {
            int n = n0 + tx * 8 + jp * 2;
            float2 v = upk2(acc[i][jp]);
            float2 outv = make_float2(v.x + biasn[jp * 2], v.y + biasn[jp * 2 + 1]);
            *reinterpret_cast<float2*>(&Cd[(size_t)m * 512 + n]) = outv;
        }
    }
}

// ---------------------------------------------------------------------------
// Kernel 3: LSTM recurrence. 256 threads per CTA, one CTA per (dir, batch).
//   Thread (j, p): j = hidden unit 0..127, p = k-half 0..1 (k in [64p,64p+64)).
//   Register weights: i,f,g gates as consecutive-k f32x2 pairs (192 regs).
//   Smem weights:     o gate (64 floats per thread row, padded rows).
//   Per step: partial dots -> smem reduce -> p0 does activations -> h to smem.
// ---------------------------------------------------------------------------
#define WO_STRIDE 68                        /* floats per padded o-row       */
#define WO_FLOATS (256 * WO_STRIDE)         /* 17408 floats                  */
#define RED_OFF   WO_FLOATS                 /* red: 4*256 ull = 2048 floats  */
#define HV_OFF    (WO_FLOATS + 2048)        /* hvec: 128 floats              */
#define LSTM2_SMEM ((HV_OFF + 160) * 4)

__global__ __launch_bounds__(256, 1)
void lstm2(const float* __restrict__ xg,
           const float* __restrict__ whh,
           const float* __restrict__ hx0,
           const float* __restrict__ cx0,
           float* __restrict__ y,
           int final_layer) {
    extern __shared__ float sm[];
    float* Wo_s = sm;
    ull*   red  = reinterpret_cast<ull*>(sm + RED_OFF);
    float* hvec = sm + HV_OFF;

    const int tid = threadIdx.x;
    const int j   = tid & 127;
    const int p   = tid >> 7;
    const int d   = blockIdx.x >> 6;
    const int b   = blockIdx.x & 63;
    const int kb  = p << 6;                 // 0 or 64

    const float* W = whh + (size_t)d * 512 * 128;

    // ---- one-time: o-gate to smem (coalesced global reads) ----------------
    for (int idx = tid; idx < 128 * 128; idx += 256) {
        int r = idx >> 7, k = idx & 127;
        float v = W[(size_t)(384 + r) * 128 + k];
        Wo_s[((k >> 6) * 128 + r) * WO_STRIDE + (k & 63)] = v;
    }

    // ---- one-time: i,f,g weights into registers as {w_k, w_k+1} pairs -----
    ull Wi[32], Wf[32], Wg[32];
    {
        const float2* ri = reinterpret_cast<const float2*>(W + (size_t)(0   + j) * 128 + kb);
        const float2* rf = reinterpret_cast<const float2*>(W + (size_t)(128 + j) * 128 + kb);
        const float2* rg = reinterpret_cast<const float2*>(W + (size_t)(256 + j) * 128 + kb);
#pragma unroll
        for (int q = 0; q < 32; q++) {
            float2 a = ri[q]; Wi[q] = pk2(a.x, a.y);
            float2 f = rf[q]; Wf[q] = pk2(f.x, f.y);
            float2 g = rg[q]; Wg[q] = pk2(g.x, g.y);
        }
    }

    float c = cx0[(size_t)(d * 64 + b) * 128 + j];
    if (tid < 128) hvec[tid] = hx0[(size_t)(d * 64 + b) * 128 + tid];
    __syncthreads();

    const int t0 = d ? (TT - 1) : 0;
    const int dt = d ? -1 : 1;
    const int nsteps = (final_layer && d) ? 1 : TT;
    const float* xgb = xg + ((size_t)d * MMM + (size_t)b * TT) * 512;

    float xi = 0.f, xf = 0.f, xgv = 0.f, xo = 0.f;
    if (p == 0) {
        const size_t bse = (size_t)t0 * 512;
        xi  = xgb[bse + j];
        xf  = xgb[bse + 128 + j];
        xgv = xgb[bse + 256 + j];
        xo  = xgb[bse + 384 + j];
    }

    const float* worow = Wo_s + (size_t)tid * WO_STRIDE;
    const float* hbase = hvec + kb;

    for (int s = 0; s < nsteps; s++) {
        const int t = t0 + s * dt;

        // ---- partial dot over this thread's k-half ------------------------
        ull aI = 0ull, aF = 0ull, aG = 0ull, aO = 0ull;
#pragma unroll
        for (int q4 = 0; q4 < 16; q4++) {
            ulonglong2 hq = *reinterpret_cast<const ulonglong2*>(hbase + 4 * q4);
            ulonglong2 wq = *reinterpret_cast<const ulonglong2*>(worow + 4 * q4);
            aI = fma2(hq.x, Wi[2 * q4], aI);
            aF = fma2(hq.x, Wf[2 * q4], aF);
            aG = fma2(hq.x, Wg[2 * q4], aG);
            aO = fma2(hq.x, wq.x,       aO);
            aI = fma2(hq.y, Wi[2 * q4 + 1], aI);
            aF = fma2(hq.y, Wf[2 * q4 + 1], aF);
            aG = fma2(hq.y, Wg[2 * q4 + 1], aG);
            aO = fma2(hq.y, wq.y,           aO);
        }
        red[0 * 256 + tid] = aI;
        red[1 * 256 + tid] = aF;
        red[2 * 256 + tid] = aG;
        red[3 * 256 + tid] = aO;
        __syncthreads();

        // ---- prefetch next xg (p0 only) -----------------------------------
        float nxi = 0.f, nxf = 0.f, nxg = 0.f, nxo = 0.f;
        if (p == 0 && s + 1 < nsteps) {
            const size_t bse = (size_t)(t + dt) * 512;
            nxi = xgb[bse + j];
            nxf = xgb[bse + 128 + j];
            nxg = xgb[bse + 256 + j];
            nxo = xgb[bse + 384 + j];
        }

        // ---- reduce + activations + h update (p0 only) --------------------
        if (p == 0) {
            float ai = hsum2(add2(red[0 * 256 + j], red[0 * 256 + 128 + j])) + xi;
            float af = hsum2(add2(red[1 * 256 + j], red[1 * 256 + 128 + j])) + xf;
            float ag = hsum2(add2(red[2 * 256 + j], red[2 * 256 + 128 + j])) + xgv;
            float ao = hsum2(add2(red[3 * 256 + j], red[3 * 256 + 128 + j])) + xo;

            float ig = sig_f(ai);
            float fg = sig_f(af);
            float og = sig_f(ao);
            c = fmaf(fg, c, ig * tanh_f(ag));
            float hn = og * tanh_f(c);

            hvec[j] = hn;
            if (!final_layer) {
                y[((size_t)b * TT + t) * 256 + d * 128 + j] = hn;
            } else if (s == nsteps - 1) {
                y[(size_t)b * 256 + d * 128 + j] = hn;
            }
        }
        __syncthreads();

        xi = nxi; xf = nxf; xgv = nxg; xo = nxo;
    }
}

// ---------------------------------------------------------------------------
// Kernel 4: linear head
// ---------------------------------------------------------------------------
__global__ void head_k(const float* __restrict__ ylast,
                       const float* __restrict__ w,
                       const float* __restrict__ bsc,
                       float* __restrict__ out) {
    int b = blockIdx.x;
    int l = threadIdx.x;
    float s = 0.f;
#pragma unroll
    for (int k = l; k < 256; k += 32) s += ylast[(size_t)b * 256 + k] * w[k];
#pragma unroll
    for (int o = 16; o; o >>= 1) s += __shfl_xor_sync(0xffffffffu, s, o);
    if (l == 0) out[b] = s + bsc[0];
}

// ---------------------------------------------------------------------------
// Host launcher
// ---------------------------------------------------------------------------
extern "C" void kernel_launch(void* const* d_in, const int* in_sizes, int n_in,
                              void* d_out, int out_size) {
    const int*   X     = (const int*)d_in[0];
    const float* emb   = (const float*)d_in[1];
    const float* hx    = (const float*)d_in[2];
    const float* cx    = (const float*)d_in[3];
    const float* lin_w = (const float*)d_in[4];
    const float* lin_b = (const float*)d_in[5];
    const float* w_ih[3] = {(const float*)d_in[6],  (const float*)d_in[10], (const float*)d_in[14]};
    const float* w_hh[3] = {(const float*)d_in[7],  (const float*)d_in[11], (const float*)d_in[15]};
    const float* b_ih[3] = {(const float*)d_in[8],  (const float*)d_in[12], (const float*)d_in[16]};
    const float* b_hh[3] = {(const float*)d_in[9],  (const float*)d_in[13], (const float*)d_in[17]};
    float* out = (float*)d_out;

    float *x0, *xgp, *ya, *yb, *ylast;
    cudaGetSymbolAddress((void**)&x0,    g_x0);
    cudaGetSymbolAddress((void**)&xgp,   g_xg);
    cudaGetSymbolAddress((void**)&ya,    g_ya);
    cudaGetSymbolAddress((void**)&yb,    g_yb);
    cudaGetSymbolAddress((void**)&ylast, g_ylast);

    cudaFuncSetAttribute(lstm2,
                         cudaFuncAttributeMaxDynamicSharedMemorySize, LSTM2_SMEM);

    embed_k<<<(MMM * 32) / 256, 256>>>(X, emb, x0);

    gemm_xw<<<dim3(512 / GBN, MMM / GBM, 2), 256>>>(x0, w_ih[0], b_ih[0], b_hh[0], xgp, 128);
    lstm2<<<128, 256, LSTM2_SMEM>>>(xgp, w_hh[0], hx + 0 * BB * 128, cx + 0 * BB * 128, ya, 0);

    gemm_xw<<<dim3(512 / GBN, MMM / GBM, 2), 256>>>(ya, w_ih[1], b_ih[1], b_hh[1], xgp, 256);
    lstm2<<<128, 256, LSTM2_SMEM>>>(xgp, w_hh[1], hx + 2 * BB * 128, cx + 2 * BB * 128, yb, 0);

    gemm_xw<<<dim3(512 / GBN, MMM / GBM, 2), 256>>>(yb, w_ih[2], b_ih[2], b_hh[2], xgp, 256);
    lstm2<<<128, 256, LSTM2_SMEM>>>(xgp, w_hh[2], hx + 4 * BB * 128, cx + 4 * BB * 128, ylast, 1);

    head_k<<<BB, 32>>>(ylast, lin_w, lin_b, out);
}

// round 4
// speedup vs baseline: 1.5834x; 1.1666x over previous
#include <cuda_runtime.h>
#include <cuda_bf16.h>

typedef unsigned long long ull;

// ---------------------------------------------------------------------------
// Problem constants
// ---------------------------------------------------------------------------
#define BB    64
#define TT    512
#define MMM   (BB * TT)        /* 32768 rows (b,t) */

// ---------------------------------------------------------------------------
// Scratch (static __device__ arrays -- allocation-free)
// ---------------------------------------------------------------------------
__device__ float g_x0[MMM * 128];
__device__ float g_xg[2u * MMM * 512];
__device__ float g_xgB[BB * 512];          // layer-2 bwd, last timestep only
__device__ float g_ya[MMM * 256];
__device__ float g_yb[MMM * 256];
__device__ float g_ylast[BB * 256];

// ---------------------------------------------------------------------------
// f32x2 packed helpers
// ---------------------------------------------------------------------------
__device__ __forceinline__ ull pk2(float lo, float hi) {
    ull r; asm("mov.b64 %0, {%1, %2};" : "=l"(r) : "f"(lo), "f"(hi)); return r;
}
__device__ __forceinline__ ull fma2(ull a, ull b, ull c) {
    ull d; asm("fma.rn.f32x2 %0, %1, %2, %3;" : "=l"(d) : "l"(a), "l"(b), "l"(c)); return d;
}
__device__ __forceinline__ ull add2(ull a, ull b) {
    ull d; asm("add.rn.f32x2 %0, %1, %2;" : "=l"(d) : "l"(a), "l"(b)); return d;
}
__device__ __forceinline__ float2 upk2(ull v) {
    float2 f; asm("mov.b64 {%0, %1}, %2;" : "=f"(f.x), "=f"(f.y) : "l"(v)); return f;
}
__device__ __forceinline__ float hsum2(ull v) { float2 f = upk2(v); return f.x + f.y; }

__device__ __forceinline__ float sig_f(float x) {
    return __fdividef(1.f, 1.f + __expf(-x));
}
__device__ __forceinline__ float tanh_f(float x) {
    return 1.f - __fdividef(2.f, 1.f + __expf(2.f * x));
}

// ---------------------------------------------------------------------------
// Kernel 1: embedding gather
// ---------------------------------------------------------------------------
__global__ void embed_k(const int* __restrict__ X,
                        const float* __restrict__ emb,
                        float* __restrict__ out) {
    int i = blockIdx.x * blockDim.x + threadIdx.x;
    int m  = i >> 5;
    int e4 = (i & 31) << 2;
    int v  = X[m];
    *reinterpret_cast<float4*>(&out[(size_t)m * 128 + e4]) =
        *reinterpret_cast<const float4*>(&emb[(size_t)v * 128 + e4]);
}

// ---------------------------------------------------------------------------
// Kernel 2: input GEMM, double-buffered smem, 2 CTAs/SM.
//   C[d][m][n] = sum_k X[m][k]*W[d][n][k] + bi[d][n] + bh[d][n]
// ---------------------------------------------------------------------------
#define GBM 128
#define GBN 128
#define GBK 16

__global__ __launch_bounds__(256, 2)
void gemm_xw(const float* __restrict__ X,
             const float* __restrict__ Wfull,
             const float* __restrict__ bi,
             const float* __restrict__ bh,
             float* __restrict__ C,
             int K) {
    const int d  = blockIdx.z;
    const float* Wd = Wfull + (size_t)d * 512 * K;
    float* Cd       = C     + (size_t)d * MMM * 512;

    __shared__ float As[2][GBK][GBM];
    __shared__ float Bs[2][GBK][GBN];

    const int m0 = blockIdx.y * GBM;
    const int n0 = blockIdx.x * GBN;
    const int tid = threadIdx.x;
    const int tx = tid & 15;
    const int ty = tid >> 4;

    const int r0l = tid >> 2,          kq0 = (tid & 3) << 2;
    const int r1l = (tid + 256) >> 2,  kq1 = ((tid + 256) & 3) << 2;

    ull acc[8][4];
#pragma unroll
    for (int i = 0; i < 8; i++)
#pragma unroll
        for (int jp = 0; jp < 4; jp++) acc[i][jp] = 0ull;

    float4 av0 = *reinterpret_cast<const float4*>(&X [(size_t)(m0 + r0l) * K + kq0]);
    float4 av1 = *reinterpret_cast<const float4*>(&X [(size_t)(m0 + r1l) * K + kq1]);
    float4 bv0 = *reinterpret_cast<const float4*>(&Wd[(size_t)(n0 + r0l) * K + kq0]);
    float4 bv1 = *reinterpret_cast<const float4*>(&Wd[(size_t)(n0 + r1l) * K + kq1]);
    {
        As[0][kq0 + 0][r0l] = av0.x; As[0][kq0 + 1][r0l] = av0.y;
        As[0][kq0 + 2][r0l] = av0.z; As[0][kq0 + 3][r0l] = av0.w;
        As[0][kq1 + 0][r1l] = av1.x; As[0][kq1 + 1][r1l] = av1.y;
        As[0][kq1 + 2][r1l] = av1.z; As[0][kq1 + 3][r1l] = av1.w;
        Bs[0][kq0 + 0][r0l] = bv0.x; Bs[0][kq0 + 1][r0l] = bv0.y;
        Bs[0][kq0 + 2][r0l] = bv0.z; Bs[0][kq0 + 3][r0l] = bv0.w;
        Bs[0][kq1 + 0][r1l] = bv1.x; Bs[0][kq1 + 1][r1l] = bv1.y;
        Bs[0][kq1 + 2][r1l] = bv1.z; Bs[0][kq1 + 3][r1l] = bv1.w;
    }
    __syncthreads();

    int buf = 0;
    for (int k0 = 0; k0 < K; k0 += GBK) {
        const bool more = (k0 + GBK) < K;
        if (more) {
            const int kn = k0 + GBK;
            av0 = *reinterpret_cast<const float4*>(&X [(size_t)(m0 + r0l) * K + kn + kq0]);
            av1 = *reinterpret_cast<const float4*>(&X [(size_t)(m0 + r1l) * K + kn + kq1]);
            bv0 = *reinterpret_cast<const float4*>(&Wd[(size_t)(n0 + r0l) * K + kn + kq0]);
            bv1 = *reinterpret_cast<const float4*>(&Wd[(size_t)(n0 + r1l) * K + kn + kq1]);
        }

#pragma unroll
        for (int k = 0; k < GBK; k++) {
            float4 a0 = *reinterpret_cast<const float4*>(&As[buf][k][ty * 8]);
            float4 a1 = *reinterpret_cast<const float4*>(&As[buf][k][ty * 8 + 4]);
            const ull* bp = reinterpret_cast<const ull*>(&Bs[buf][k][tx * 8]);
            ull b0 = bp[0], b1 = bp[1], b2 = bp[2], b3 = bp[3];
            float aa[8] = {a0.x, a0.y, a0.z, a0.w, a1.x, a1.y, a1.z, a1.w};
#pragma unroll
            for (int i = 0; i < 8; i++) {
                ull ap = pk2(aa[i], aa[i]);
                acc[i][0] = fma2(ap, b0, acc[i][0]);
                acc[i][1] = fma2(ap, b1, acc[i][1]);
                acc[i][2] = fma2(ap, b2, acc[i][2]);
                acc[i][3] = fma2(ap, b3, acc[i][3]);
            }
        }

        if (more) {
            const int nb = buf ^ 1;
            As[nb][kq0 + 0][r0l] = av0.x; As[nb][kq0 + 1][r0l] = av0.y;
            As[nb][kq0 + 2][r0l] = av0.z; As[nb][kq0 + 3][r0l] = av0.w;
            As[nb][kq1 + 0][r1l] = av1.x; As[nb][kq1 + 1][r1l] = av1.y;
            As[nb][kq1 + 2][r1l] = av1.z; As[nb][kq1 + 3][r1l] = av1.w;
            Bs[nb][kq0 + 0][r0l] = bv0.x; Bs[nb][kq0 + 1][r0l] = bv0.y;
            Bs[nb][kq0 + 2][r0l] = bv0.z; Bs[nb][kq0 + 3][r0l] = bv0.w;
            Bs[nb][kq1 + 0][r1l] = bv1.x; Bs[nb][kq1 + 1][r1l] = bv1.y;
            Bs[nb][kq1 + 2][r1l] = bv1.z; Bs[nb][kq1 + 3][r1l] = bv1.w;
            __syncthreads();
            buf = nb;
        }
    }

    float biasn[8];
#pragma unroll
    for (int q = 0; q < 8; q++) {
        int n = n0 + tx * 8 + q;
        biasn[q] = bi[d * 512 + n] + bh[d * 512 + n];
    }
#pragma unroll
    for (int i = 0; i < 8; i++) {
        int m = m0 + ty * 8 + i;
        float2 v0 = upk2(acc[i][0]);
        float2 v1 = upk2(acc[i][1]);
        float2 v2 = upk2(acc[i][2]);
        float2 v3 = upk2(acc[i][3]);
        float4 o0 = make_float4(v0.x + biasn[0], v0.y + biasn[1],
                                v1.x + biasn[2], v1.y + biasn[3]);
        float4 o1 = make_float4(v2.x + biasn[4], v2.y + biasn[5],
                                v3.x + biasn[6], v3.y + biasn[7]);
        *reinterpret_cast<float4*>(&Cd[(size_t)m * 512 + n0 + tx * 8 + 0]) = o0;
        *reinterpret_cast<float4*>(&Cd[(size_t)m * 512 + n0 + tx * 8 + 4]) = o1;
    }
}

// ---------------------------------------------------------------------------
// Kernel 2b: layer-2 backward needs xg only at t = T-1  ->  tiny GEMV.
//   out[b][n] = sum_k y[(b*T + T-1)*256 + k] * W[1][n][k] + bi[1][n] + bh[1][n]
// ---------------------------------------------------------------------------
__global__ __launch_bounds__(256)
void gemv_last(const float* __restrict__ y,
               const float* __restrict__ Wfull,
               const float* __restrict__ bi,
               const float* __restrict__ bh,
               float* __restrict__ out) {
    __shared__ float xr[256];
    const int b = blockIdx.x;
    const float* x = y + ((size_t)b * TT + (TT - 1)) * 256;
    xr[threadIdx.x] = x[threadIdx.x];
    __syncthreads();
#pragma unroll
    for (int nn = 0; nn < 2; nn++) {
        int n = threadIdx.x + nn * 256;
        const float* wr = Wfull + (size_t)(512 + n) * 256;   // direction 1
        ull s2 = 0ull;
        const ull* xp = reinterpret_cast<const ull*>(xr);
        const ull* wp = reinterpret_cast<const ull*>(wr);
#pragma unroll
        for (int k = 0; k < 128; k++) s2 = fma2(xp[k], wp[k], s2);
        out[(size_t)b * 512 + n] = hsum2(s2) + bi[512 + n] + bh[512 + n];
    }
}

// ---------------------------------------------------------------------------
// Kernel 3: LSTM recurrence. 256 threads per CTA, one CTA per (dir, batch).
// ---------------------------------------------------------------------------
#define WO_STRIDE 68
#define WO_FLOATS (256 * WO_STRIDE)
#define RED_OFF   WO_FLOATS
#define HV_OFF    (WO_FLOATS + 2048)
#define LSTM2_SMEM ((HV_OFF + 160) * 4)

__global__ __launch_bounds__(256, 1)
void lstm2(const float* __restrict__ xg,
           const float* __restrict__ xgB,     // layer-2 bwd last-t buffer
           const float* __restrict__ whh,
           const float* __restrict__ hx0,
           const float* __restrict__ cx0,
           float* __restrict__ y,
           int final_layer) {
    extern __shared__ float sm[];
    float* Wo_s = sm;
    ull*   red  = reinterpret_cast<ull*>(sm + RED_OFF);
    float* hvec = sm + HV_OFF;

    const int tid = threadIdx.x;
    const int j   = tid & 127;
    const int p   = tid >> 7;
    const int d   = blockIdx.x >> 6;
    const int b   = blockIdx.x & 63;
    const int kb  = p << 6;

    const float* W = whh + (size_t)d * 512 * 128;

    for (int idx = tid; idx < 128 * 128; idx += 256) {
        int r = idx >> 7, k = idx & 127;
        float v = W[(size_t)(384 + r) * 128 + k];
        Wo_s[((k >> 6) * 128 + r) * WO_STRIDE + (k & 63)] = v;
    }

    ull Wi[32], Wf[32], Wg[32];
    {
        const float2* ri = reinterpret_cast<const float2*>(W + (size_t)(0   + j) * 128 + kb);
        const float2* rf = reinterpret_cast<const float2*>(W + (size_t)(128 + j) * 128 + kb);
        const float2* rg = reinterpret_cast<const float2*>(W + (size_t)(256 + j) * 128 + kb);
#pragma unroll
        for (int q = 0; q < 32; q++) {
            float2 a = ri[q]; Wi[q] = pk2(a.x, a.y);
            float2 f = rf[q]; Wf[q] = pk2(f.x, f.y);
            float2 g = rg[q]; Wg[q] = pk2(g.x, g.y);
        }
    }

    float c = cx0[(size_t)(d * 64 + b) * 128 + j];
    if (tid < 128) hvec[tid] = hx0[(size_t)(d * 64 + b) * 128 + tid];
    __syncthreads();

    const int t0 = d ? (TT - 1) : 0;
    const int dt = d ? -1 : 1;
    const bool bwd_last = (final_layer && d);
    const int nsteps = bwd_last ? 1 : TT;
    const float* xgb = xg + ((size_t)d * MMM + (size_t)b * TT) * 512;

    float xi = 0.f, xf = 0.f, xgv = 0.f, xo = 0.f;
    if (p == 0) {
        const float* row = bwd_last ? (xgB + (size_t)b * 512)
                                    : (xgb + (size_t)t0 * 512);
        xi  = row[j];
        xf  = row[128 + j];
        xgv = row[256 + j];
        xo  = row[384 + j];
    }

    const float* worow = Wo_s + (size_t)tid * WO_STRIDE;
    const float* hbase = hvec + kb;

    for (int s = 0; s < nsteps; s++) {
        const int t = t0 + s * dt;

        ull aI = 0ull, aF = 0ull, aG = 0ull, aO = 0ull;
#pragma unroll
        for (int q4 = 0; q4 < 16; q4++) {
            ulonglong2 hq = *reinterpret_cast<const ulonglong2*>(hbase + 4 * q4);
            ulonglong2 wq = *reinterpret_cast<const ulonglong2*>(worow + 4 * q4);
            aI = fma2(hq.x, Wi[2 * q4], aI);
            aF = fma2(hq.x, Wf[2 * q4], aF);
            aG = fma2(hq.x, Wg[2 * q4], aG);
            aO = fma2(hq.x, wq.x,       aO);
            aI = fma2(hq.y, Wi[2 * q4 + 1], aI);
            aF = fma2(hq.y, Wf[2 * q4 + 1], aF);
            aG = fma2(hq.y, Wg[2 * q4 + 1], aG);
            aO = fma2(hq.y, wq.y,           aO);
        }
        red[0 * 256 + tid] = aI;
        red[1 * 256 + tid] = aF;
        red[2 * 256 + tid] = aG;
        red[3 * 256 + tid] = aO;
        __syncthreads();

        float nxi = 0.f, nxf = 0.f, nxg = 0.f, nxo = 0.f;
        if (p == 0 && s + 1 < nsteps) {
            const size_t bse = (size_t)(t + dt) * 512;
            nxi = xgb[bse + j];
            nxf = xgb[bse + 128 + j];
            nxg = xgb[bse + 256 + j];
            nxo = xgb[bse + 384 + j];
        }

        if (p == 0) {
            float ai = hsum2(add2(red[0 * 256 + j], red[0 * 256 + 128 + j])) + xi;
            float af = hsum2(add2(red[1 * 256 + j], red[1 * 256 + 128 + j])) + xf;
            float ag = hsum2(add2(red[2 * 256 + j], red[2 * 256 + 128 + j])) + xgv;
            float ao = hsum2(add2(red[3 * 256 + j], red[3 * 256 + 128 + j])) + xo;

            float ig = sig_f(ai);
            float fg = sig_f(af);
            float og = sig_f(ao);
            c = fmaf(fg, c, ig * tanh_f(ag));
            float hn = og * tanh_f(c);

            hvec[j] = hn;
            if (!final_layer) {
                y[((size_t)b * TT + t) * 256 + d * 128 + j] = hn;
            } else if (s == nsteps - 1) {
                y[(size_t)b * 256 + d * 128 + j] = hn;
            }
        }
        __syncthreads();

        xi = nxi; xf = nxf; xgv = nxg; xo = nxo;
    }
}

// ---------------------------------------------------------------------------
// Kernel 4: linear head
// ---------------------------------------------------------------------------
__global__ void head_k(const float* __restrict__ ylast,
                       const float* __restrict__ w,
                       const float* __restrict__ bsc,
                       float* __restrict__ out) {
    int b = blockIdx.x;
    int l = threadIdx.x;
    float s = 0.f;
#pragma unroll
    for (int k = l; k < 256; k += 32) s += ylast[(size_t)b * 256 + k] * w[k];
#pragma unroll
    for (int o = 16; o; o >>= 1) s += __shfl_xor_sync(0xffffffffu, s, o);
    if (l == 0) out[b] = s + bsc[0];
}

// ---------------------------------------------------------------------------
// Host launcher
// ---------------------------------------------------------------------------
extern "C" void kernel_launch(void* const* d_in, const int* in_sizes, int n_in,
                              void* d_out, int out_size) {
    const int*   X     = (const int*)d_in[0];
    const float* emb   = (const float*)d_in[1];
    const float* hx    = (const float*)d_in[2];
    const float* cx    = (const float*)d_in[3];
    const float* lin_w = (const float*)d_in[4];
    const float* lin_b = (const float*)d_in[5];
    const float* w_ih[3] = {(const float*)d_in[6],  (const float*)d_in[10], (const float*)d_in[14]};
    const float* w_hh[3] = {(const float*)d_in[7],  (const float*)d_in[11], (const float*)d_in[15]};
    const float* b_ih[3] = {(const float*)d_in[8],  (const float*)d_in[12], (const float*)d_in[16]};
    const float* b_hh[3] = {(const float*)d_in[9],  (const float*)d_in[13], (const float*)d_in[17]};
    float* out = (float*)d_out;

    float *x0, *xgp, *xgB, *ya, *yb, *ylast;
    cudaGetSymbolAddress((void**)&x0,    g_x0);
    cudaGetSymbolAddress((void**)&xgp,   g_xg);
    cudaGetSymbolAddress((void**)&xgB,   g_xgB);
    cudaGetSymbolAddress((void**)&ya,    g_ya);
    cudaGetSymbolAddress((void**)&yb,    g_yb);
    cudaGetSymbolAddress((void**)&ylast, g_ylast);

    cudaFuncSetAttribute(lstm2,
                         cudaFuncAttributeMaxDynamicSharedMemorySize, LSTM2_SMEM);

    embed_k<<<(MMM * 32) / 256, 256>>>(X, emb, x0);

    gemm_xw<<<dim3(512 / GBN, MMM / GBM, 2), 256>>>(x0, w_ih[0], b_ih[0], b_hh[0], xgp, 128);
    lstm2<<<128, 256, LSTM2_SMEM>>>(xgp, nullptr, w_hh[0], hx + 0 * BB * 128, cx + 0 * BB * 128, ya, 0);

    gemm_xw<<<dim3(512 / GBN, MMM / GBM, 2), 256>>>(ya, w_ih[1], b_ih[1], b_hh[1], xgp, 256);
    lstm2<<<128, 256, LSTM2_SMEM>>>(xgp, nullptr, w_hh[1], hx + 2 * BB * 128, cx + 2 * BB * 128, yb, 0);

    // layer 2: forward direction needs full xg; backward needs only t = T-1
    gemm_xw<<<dim3(512 / GBN, MMM / GBM, 1), 256>>>(yb, w_ih[2], b_ih[2], b_hh[2], xgp, 256);
    gemv_last<<<BB, 256>>>(yb, w_ih[2], b_ih[2], b_hh[2], xgB);
    lstm2<<<128, 256, LSTM2_SMEM>>>(xgp, xgB, w_hh[2], hx + 4 * BB * 128, cx + 4 * BB * 128, ylast, 1);

    head_k<<<BB, 32>>>(ylast, lin_w, lin_b, out);
}